// round 5
// baseline (speedup 1.0000x reference)
#include <cuda_runtime.h>

// graphDenoising: per-(b,n) rank-1 bilinear scores + sigmoid.
// Best-measured structure (R1: warp-per-row, 256-thread blocks, regs 32,
// DRAM 92.6%) + streaming-load hints + smem-staged coalesced output stores.
// This kernel is at the HBM roofline: 1.61 GB read once @ ~7.3 TB/s.

#define DIM 256
#define THREADS 256
#define WARPS_PER_BLOCK (THREADS / 32)

__global__ __launch_bounds__(THREADS)
void graph_denoise_kernel(const float* __restrict__ user_emb,
                          const float* __restrict__ pos_emb,
                          const float* __restrict__ neg_emb,
                          const float* __restrict__ beh_emb,
                          const float* __restrict__ prompt_emb,
                          float* __restrict__ out,
                          int N, int B)
{
    __shared__ float s_res[2][WARPS_PER_BLOCK];   // [pos/neg][warp]

    const int tid = threadIdx.x;
    const int warp_in_blk = tid >> 5;
    const int lane = tid & 31;
    const int warp_id = blockIdx.x * WARPS_PER_BLOCK + warp_in_blk;
    const int total = B * N;
    if (warp_id >= total) return;

    // A block's 8 rows are consecutive; N % 8 == 0 => one behavior per block.
    const int b = warp_id / N;
    const int n = warp_id - b * N;

    const float4* w4 = (b < B - 1)
        ? reinterpret_cast<const float4*>(beh_emb + (size_t)b * DIM)
        : reinterpret_cast<const float4*>(prompt_emb);
    const float4 w0 = w4[lane];
    const float4 w1 = w4[lane + 32];

    const size_t base = (size_t)warp_id * DIM;
    const float4* u4 = reinterpret_cast<const float4*>(user_emb + base);
    const float4* p4 = reinterpret_cast<const float4*>(pos_emb  + base);
    const float4* g4 = reinterpret_cast<const float4*>(neg_emb  + base);

    // 6 independent streaming LDG.128 (read-once -> evict-first)
    const float4 a0 = __ldcs(u4 + lane), a1 = __ldcs(u4 + lane + 32);
    const float4 b0 = __ldcs(p4 + lane), b1 = __ldcs(p4 + lane + 32);
    const float4 c0 = __ldcs(g4 + lane), c1 = __ldcs(g4 + lane + 32);

    float du = a0.x * w0.x;
    du = fmaf(a0.y, w0.y, du); du = fmaf(a0.z, w0.z, du); du = fmaf(a0.w, w0.w, du);
    du = fmaf(a1.x, w1.x, du); du = fmaf(a1.y, w1.y, du);
    du = fmaf(a1.z, w1.z, du); du = fmaf(a1.w, w1.w, du);

    float dp = b0.x * w0.x;
    dp = fmaf(b0.y, w0.y, dp); dp = fmaf(b0.z, w0.z, dp); dp = fmaf(b0.w, w0.w, dp);
    dp = fmaf(b1.x, w1.x, dp); dp = fmaf(b1.y, w1.y, dp);
    dp = fmaf(b1.z, w1.z, dp); dp = fmaf(b1.w, w1.w, dp);

    float dg = c0.x * w0.x;
    dg = fmaf(c0.y, w0.y, dg); dg = fmaf(c0.z, w0.z, dg); dg = fmaf(c0.w, w0.w, dg);
    dg = fmaf(c1.x, w1.x, dg); dg = fmaf(c1.y, w1.y, dg);
    dg = fmaf(c1.z, w1.z, dg); dg = fmaf(c1.w, w1.w, dg);

    #pragma unroll
    for (int off = 16; off > 0; off >>= 1) {
        du += __shfl_xor_sync(0xffffffffu, du, off);
        dp += __shfl_xor_sync(0xffffffffu, dp, off);
        dg += __shfl_xor_sync(0xffffffffu, dg, off);
    }

    if (lane == 0) {
        s_res[0][warp_in_blk] = 1.0f / (1.0f + __expf(-(du * dp)));
        s_res[1][warp_in_blk] = 1.0f / (1.0f + __expf(-(du * dg)));
    }
    __syncthreads();

    // Coalesced stores: 8 consecutive pos results + 8 consecutive neg
    // results per block -> two contiguous 32B segments.
    if (tid < 2 * WARPS_PER_BLOCK) {
        const int half = tid / WARPS_PER_BLOCK;     // 0 = pos, 1 = neg
        const int i    = tid - half * WARPS_PER_BLOCK;
        const int n0   = n;                          // lane==... n of warp 0? no:
        // recompute block-first n from warp 0 of this block:
        const int row0 = blockIdx.x * WARPS_PER_BLOCK;
        const int bb   = row0 / N;
        const int nb   = row0 - bb * N;
        float* ob = out + (size_t)bb * 2 * N;
        ob[half * N + nb + i] = s_res[half][i];
        (void)n0;
    }
}

extern "C" void kernel_launch(void* const* d_in, const int* in_sizes, int n_in,
                              void* d_out, int out_size)
{
    const float* user_emb   = (const float*)d_in[0];
    const float* pos_emb    = (const float*)d_in[1];
    const float* neg_emb    = (const float*)d_in[2];
    const float* beh_emb    = (const float*)d_in[3];
    const float* prompt_emb = (const float*)d_in[4];
    float* out = (float*)d_out;

    const int B = in_sizes[3] / DIM;            // 4
    const int N = in_sizes[0] / (B * DIM);      // 131072

    const int total_warps = B * N;               // 524288
    const int blocks = (total_warps + WARPS_PER_BLOCK - 1) / WARPS_PER_BLOCK;  // 65536

    graph_denoise_kernel<<<blocks, THREADS>>>(user_emb, pos_emb, neg_emb,
                                              beh_emb, prompt_emb, out, N, B);
}

// round 6
// speedup vs baseline: 1.1045x; 1.1045x over previous
#include <cuda_runtime.h>

// graphDenoising: per-(b,n) rank-1 bilinear scores + sigmoid.
//   w[b] = beh_emb[b] for b < B-1, prompt_emb for b = B-1
//   u = dot(user[b,n], w[b]); p = dot(pos[b,n], w[b]); g = dot(neg[b,n], w[b])
//   out[b, n] = sigmoid(u*p);  out[b, N+n] = sigmoid(u*g)
//
// FINAL: exact Round-1 structure — warp per row, 256-thread blocks, 6
// coalesced LDG.128 per lane, butterfly reduce, lane-0 store. Measured
// best of 5 structural variants: 220.6 us kernel, DRAM 92.6% (7.34 TB/s).
// All alternatives (row pairing, software pipelining, 1024T blocks,
// smem-staged stores) measured worse; this is the HBM roofline.

#define DIM 256

__global__ __launch_bounds__(256)
void graph_denoise_kernel(const float* __restrict__ user_emb,
                          const float* __restrict__ pos_emb,
                          const float* __restrict__ neg_emb,
                          const float* __restrict__ beh_emb,
                          const float* __restrict__ prompt_emb,
                          float* __restrict__ out,
                          int N, int B)
{
    const int warp_id = (blockIdx.x * blockDim.x + threadIdx.x) >> 5;
    const int lane = threadIdx.x & 31;
    const int total = B * N;
    if (warp_id >= total) return;

    const int b = warp_id / N;
    const int n = warp_id - b * N;

    // Per-behavior weight vector (L1-resident after first touch)
    const float4* w4 = (b < B - 1)
        ? reinterpret_cast<const float4*>(beh_emb + (size_t)b * DIM)
        : reinterpret_cast<const float4*>(prompt_emb);
    const float4 w0 = w4[lane];
    const float4 w1 = w4[lane + 32];

    const size_t base = (size_t)warp_id * DIM;  // (b*N + n) * DIM
    const float4* u4 = reinterpret_cast<const float4*>(user_emb + base);
    const float4* p4 = reinterpret_cast<const float4*>(pos_emb  + base);
    const float4* g4 = reinterpret_cast<const float4*>(neg_emb  + base);

    // 6 independent LDG.128 -> MLP=6 per lane
    const float4 a0 = u4[lane], a1 = u4[lane + 32];
    const float4 b0 = p4[lane], b1 = p4[lane + 32];
    const float4 c0 = g4[lane], c1 = g4[lane + 32];

    float du = a0.x * w0.x;
    du = fmaf(a0.y, w0.y, du); du = fmaf(a0.z, w0.z, du); du = fmaf(a0.w, w0.w, du);
    du = fmaf(a1.x, w1.x, du); du = fmaf(a1.y, w1.y, du);
    du = fmaf(a1.z, w1.z, du); du = fmaf(a1.w, w1.w, du);

    float dp = b0.x * w0.x;
    dp = fmaf(b0.y, w0.y, dp); dp = fmaf(b0.z, w0.z, dp); dp = fmaf(b0.w, w0.w, dp);
    dp = fmaf(b1.x, w1.x, dp); dp = fmaf(b1.y, w1.y, dp);
    dp = fmaf(b1.z, w1.z, dp); dp = fmaf(b1.w, w1.w, dp);

    float dg = c0.x * w0.x;
    dg = fmaf(c0.y, w0.y, dg); dg = fmaf(c0.z, w0.z, dg); dg = fmaf(c0.w, w0.w, dg);
    dg = fmaf(c1.x, w1.x, dg); dg = fmaf(c1.y, w1.y, dg);
    dg = fmaf(c1.z, w1.z, dg); dg = fmaf(c1.w, w1.w, dg);

    // Butterfly warp reduction for all three dots
    #pragma unroll
    for (int off = 16; off > 0; off >>= 1) {
        du += __shfl_xor_sync(0xffffffffu, du, off);
        dp += __shfl_xor_sync(0xffffffffu, dp, off);
        dg += __shfl_xor_sync(0xffffffffu, dg, off);
    }

    if (lane == 0) {
        const float xp = du * dp;
        const float xg = du * dg;
        const float sp = 1.0f / (1.0f + __expf(-xp));
        const float sg = 1.0f / (1.0f + __expf(-xg));
        float* ob = out + (size_t)b * 2 * N;
        ob[n]     = sp;
        ob[N + n] = sg;
    }
}

extern "C" void kernel_launch(void* const* d_in, const int* in_sizes, int n_in,
                              void* d_out, int out_size)
{
    const float* user_emb   = (const float*)d_in[0];
    const float* pos_emb    = (const float*)d_in[1];
    const float* neg_emb    = (const float*)d_in[2];
    const float* beh_emb    = (const float*)d_in[3];
    const float* prompt_emb = (const float*)d_in[4];
    float* out = (float*)d_out;

    const int B = in_sizes[3] / DIM;            // 4
    const int N = in_sizes[0] / (B * DIM);      // 131072

    const int total_warps = B * N;
    const int threads = 256;
    const int warps_per_block = threads / 32;
    const int blocks = (total_warps + warps_per_block - 1) / warps_per_block;

    graph_denoise_kernel<<<blocks, threads>>>(user_emb, pos_emb, neg_emb,
                                              beh_emb, prompt_emb, out, N, B);
}

// round 7
// speedup vs baseline: 1.1063x; 1.0017x over previous
#include <cuda_runtime.h>

// graphDenoising: per-(b,n) rank-1 bilinear scores + sigmoid.
//   w[b] = beh_emb[b] for b < B-1, prompt_emb for b = B-1
//   u = dot(user[b,n], w[b]); p = dot(pos[b,n], w[b]); g = dot(neg[b,n], w[b])
//   out[b, n] = sigmoid(u*p);  out[b, N+n] = sigmoid(u*g)
//
// FINAL (reproduced twice): warp per row, 256-thread blocks, 6 coalesced
// LDG.128 per lane, butterfly reduce, lane-0 store.
//   R1: 220.6 us kernel, DRAM 92.6%   R6: 219.9 us kernel, DRAM 92.9%
// All structural alternatives measured worse (row pairing 227, pipelining
// 227, 1024T blocks 223, smem-staged stores 254). 7.36 TB/s on a 1.61 GB
// single-pass stream = the achievable HBM roofline for this chip.

#define DIM 256

__global__ __launch_bounds__(256)
void graph_denoise_kernel(const float* __restrict__ user_emb,
                          const float* __restrict__ pos_emb,
                          const float* __restrict__ neg_emb,
                          const float* __restrict__ beh_emb,
                          const float* __restrict__ prompt_emb,
                          float* __restrict__ out,
                          int N, int B)
{
    const int warp_id = (blockIdx.x * blockDim.x + threadIdx.x) >> 5;
    const int lane = threadIdx.x & 31;
    const int total = B * N;
    if (warp_id >= total) return;

    const int b = warp_id / N;
    const int n = warp_id - b * N;

    // Per-behavior weight vector (L1-resident after first touch)
    const float4* w4 = (b < B - 1)
        ? reinterpret_cast<const float4*>(beh_emb + (size_t)b * DIM)
        : reinterpret_cast<const float4*>(prompt_emb);
    const float4 w0 = w4[lane];
    const float4 w1 = w4[lane + 32];

    const size_t base = (size_t)warp_id * DIM;  // (b*N + n) * DIM
    const float4* u4 = reinterpret_cast<const float4*>(user_emb + base);
    const float4* p4 = reinterpret_cast<const float4*>(pos_emb  + base);
    const float4* g4 = reinterpret_cast<const float4*>(neg_emb  + base);

    // 6 independent LDG.128 -> MLP=6 per lane
    const float4 a0 = u4[lane], a1 = u4[lane + 32];
    const float4 b0 = p4[lane], b1 = p4[lane + 32];
    const float4 c0 = g4[lane], c1 = g4[lane + 32];

    float du = a0.x * w0.x;
    du = fmaf(a0.y, w0.y, du); du = fmaf(a0.z, w0.z, du); du = fmaf(a0.w, w0.w, du);
    du = fmaf(a1.x, w1.x, du); du = fmaf(a1.y, w1.y, du);
    du = fmaf(a1.z, w1.z, du); du = fmaf(a1.w, w1.w, du);

    float dp = b0.x * w0.x;
    dp = fmaf(b0.y, w0.y, dp); dp = fmaf(b0.z, w0.z, dp); dp = fmaf(b0.w, w0.w, dp);
    dp = fmaf(b1.x, w1.x, dp); dp = fmaf(b1.y, w1.y, dp);
    dp = fmaf(b1.z, w1.z, dp); dp = fmaf(b1.w, w1.w, dp);

    float dg = c0.x * w0.x;
    dg = fmaf(c0.y, w0.y, dg); dg = fmaf(c0.z, w0.z, dg); dg = fmaf(c0.w, w0.w, dg);
    dg = fmaf(c1.x, w1.x, dg); dg = fmaf(c1.y, w1.y, dg);
    dg = fmaf(c1.z, w1.z, dg); dg = fmaf(c1.w, w1.w, dg);

    // Butterfly warp reduction for all three dots
    #pragma unroll
    for (int off = 16; off > 0; off >>= 1) {
        du += __shfl_xor_sync(0xffffffffu, du, off);
        dp += __shfl_xor_sync(0xffffffffu, dp, off);
        dg += __shfl_xor_sync(0xffffffffu, dg, off);
    }

    if (lane == 0) {
        const float xp = du * dp;
        const float xg = du * dg;
        const float sp = 1.0f / (1.0f + __expf(-xp));
        const float sg = 1.0f / (1.0f + __expf(-xg));
        float* ob = out + (size_t)b * 2 * N;
        ob[n]     = sp;
        ob[N + n] = sg;
    }
}

extern "C" void kernel_launch(void* const* d_in, const int* in_sizes, int n_in,
                              void* d_out, int out_size)
{
    const float* user_emb   = (const float*)d_in[0];
    const float* pos_emb    = (const float*)d_in[1];
    const float* neg_emb    = (const float*)d_in[2];
    const float* beh_emb    = (const float*)d_in[3];
    const float* prompt_emb = (const float*)d_in[4];
    float* out = (float*)d_out;

    const int B = in_sizes[3] / DIM;            // 4
    const int N = in_sizes[0] / (B * DIM);      // 131072

    const int total_warps = B * N;
    const int threads = 256;
    const int warps_per_block = threads / 32;
    const int blocks = (total_warps + warps_per_block - 1) / warps_per_block;

    graph_denoise_kernel<<<blocks, threads>>>(user_emb, pos_emb, neg_emb,
                                              beh_emb, prompt_emb, out, N, B);
}